// round 2
// baseline (speedup 1.0000x reference)
#include <cuda_runtime.h>
#include <cuda_bf16.h>
#include <math.h>

// Shapes (fixed by the problem)
#define BATCH   32
#define CIN     512
#define HW      196            // 14*14
#define DPROJ   8192
#define DMASK   8191

// Gram/scatter tiling
#define CH      128            // c-chunk per CTA tile (4 chunks -> 512)
#define KT      49             // K tile (4*49 = 196)
#define XS      132            // smem row stride (floats), mult of 4 for LDS.128
#define NTHR    256
#define NTILES  10             // symmetric block-tile pairs (p >= q), 4x4 blocks

typedef unsigned long long ull;

// ---- device scratch (no allocations allowed) ----
__device__ int   d_h[2][CIN];
__device__ float d_s[2][CIN];
__device__ float d_yacc[BATCH * DPROJ];

// symmetric tile enumeration: (p,q) with p >= q
__constant__ int TP[NTILES] = {0,1,1,2,2,2,3,3,3,3};
__constant__ int TQ[NTILES] = {0,0,1,0,1,2,0,1,2,3};

// ---- packed f32x2 helpers (sm_100+: FFMA2 only reachable via PTX) ----
__device__ __forceinline__ ull pack2(float x, float y) {
    ull r; asm("mov.b64 %0, {%1, %2};" : "=l"(r) : "f"(x), "f"(y)); return r;
}
__device__ __forceinline__ void unpack2(ull v, float& x, float& y) {
    asm("mov.b64 {%0, %1}, %2;" : "=f"(x), "=f"(y) : "l"(v));
}
__device__ __forceinline__ ull ffma2(ull a, ull b, ull c) {
    ull d; asm("fma.rn.f32x2 %0, %1, %2, %3;" : "=l"(d) : "l"(a), "l"(b), "l"(c));
    return d;
}

// ============================================================
// Kernel 1: extract count-sketch (h, s) from dense S1/S2.
// One warp per row; each row has exactly one nonzero (+-1).
// ============================================================
__global__ void extract_kernel(const float* __restrict__ S1,
                               const float* __restrict__ S2) {
    int wg   = (blockIdx.x << 3) + (threadIdx.x >> 5);   // 128 blocks * 8 warps = 1024
    int lane = threadIdx.x & 31;
    int m = wg >> 9;          // 0 -> S1, 1 -> S2
    int r = wg & 511;
    const float4* S4 = (const float4*)((m ? S2 : S1) + (size_t)r * DPROJ);
    for (int i = lane; i < DPROJ / 4; i += 32) {
        float4 v = S4[i];
        int base = i << 2;
        if (v.x != 0.f) { d_h[m][r] = base + 0; d_s[m][r] = v.x; }
        if (v.y != 0.f) { d_h[m][r] = base + 1; d_s[m][r] = v.y; }
        if (v.z != 0.f) { d_h[m][r] = base + 2; d_s[m][r] = v.z; }
        if (v.w != 0.f) { d_h[m][r] = base + 3; d_s[m][r] = v.w; }
    }
}

// ============================================================
// Kernel 2: zero the global accumulator (graph is replayed).
// ============================================================
__global__ void zero_kernel() {
    float4* p = (float4*)d_yacc;
    p[blockIdx.x * blockDim.x + threadIdx.x] = make_float4(0.f, 0.f, 0.f, 0.f);
}

// ============================================================
// Kernel 3: fused Gram tile + count-sketch-conv scatter.
// grid = (10 sym tiles, 32 images). Tile = 128x128 of G, thread = 8x8.
// Signs s1/s2 folded into operand tiles; off-diagonal tiles scatter
// both orientations (second orientation rescaled by t[i]*u[j]).
// ============================================================
__global__ __launch_bounds__(NTHR, 2)
void gram_scatter(const float* __restrict__ x) {
    extern __shared__ float sm[];
    float* bins = sm;                         // DPROJ floats
    float* As   = sm + DPROJ;                 // KT * XS
    float* Bs   = As + KT * XS;               // KT * XS
    float* sA   = Bs + KT * XS;               // CH signs for c1 block (s1)
    float* sB   = sA + CH;                    // CH signs for c2 block (s2)

    const int b    = blockIdx.y;
    const int p    = TP[blockIdx.x];
    const int q    = TQ[blockIdx.x];
    const int c1_0 = p * CH;
    const int c2_0 = q * CH;
    const bool offdiag = (p != q);
    const int tid  = threadIdx.x;
    const int ti   = tid >> 4;                // 0..15
    const int tj   = tid & 15;                // 0..15
    const int ao   = ti * 8;
    const int bo   = tj * 8;

    for (int l = tid; l < DPROJ; l += NTHR) bins[l] = 0.f;
    if (tid < CH)        sA[tid]        = d_s[0][c1_0 + tid];
    else                 sB[tid - CH]   = d_s[1][c2_0 + (tid - CH)];

    const float* xb = x + (size_t)b * CIN * HW;

    ull acc[8][4];
#pragma unroll
    for (int i = 0; i < 8; ++i)
#pragma unroll
        for (int j = 0; j < 4; ++j) acc[i][j] = 0ULL;

    for (int kt = 0; kt < 4; ++kt) {
        const int k0 = kt * KT;
        __syncthreads();   // protects bins/sign init (kt==0) / prev compute (kt>0)
        for (int l = tid; l < CH * KT; l += NTHR) {
            int ci = l / KT;
            int k  = l - ci * KT;
            As[k * XS + ci] = xb[(c1_0 + ci) * HW + k0 + k] * sA[ci];
            Bs[k * XS + ci] = xb[(c2_0 + ci) * HW + k0 + k] * sB[ci];
        }
        __syncthreads();

        for (int k = 0; k < KT; ++k) {
            const float* Ar = As + k * XS + ao;
            float4 a0 = *(const float4*)(Ar);
            float4 a1 = *(const float4*)(Ar + 4);
            ull ap[8];
            ap[0] = pack2(a0.x, a0.x); ap[1] = pack2(a0.y, a0.y);
            ap[2] = pack2(a0.z, a0.z); ap[3] = pack2(a0.w, a0.w);
            ap[4] = pack2(a1.x, a1.x); ap[5] = pack2(a1.y, a1.y);
            ap[6] = pack2(a1.z, a1.z); ap[7] = pack2(a1.w, a1.w);

            const float* Br = Bs + k * XS + bo;
            ulonglong2 bb0 = *(const ulonglong2*)(Br);       // pairs (b0,b1),(b2,b3)
            ulonglong2 bb1 = *(const ulonglong2*)(Br + 4);   // pairs (b4,b5),(b6,b7)
#pragma unroll
            for (int i = 0; i < 8; ++i) {
                acc[i][0] = ffma2(ap[i], bb0.x, acc[i][0]);
                acc[i][1] = ffma2(ap[i], bb0.y, acc[i][1]);
                acc[i][2] = ffma2(ap[i], bb1.x, acc[i][2]);
                acc[i][3] = ffma2(ap[i], bb1.y, acc[i][3]);
            }
        }
    }
    __syncthreads();   // all FMA traffic done before heavy bin atomics phase

    // Scatter this thread's 8x8 tile into the shared bins.
    // Orientation 1: rows are c1-block channels, cols are c2-block channels.
    int h1r[8], h2c[8];
#pragma unroll
    for (int i = 0; i < 8; ++i) h1r[i] = d_h[0][c1_0 + ao + i];
#pragma unroll
    for (int j = 0; j < 8; ++j) h2c[j] = d_h[1][c2_0 + bo + j];

#pragma unroll
    for (int i = 0; i < 8; ++i) {
#pragma unroll
        for (int jp = 0; jp < 4; ++jp) {
            float g0, g1;
            unpack2(acc[i][jp], g0, g1);
            atomicAdd(&bins[(h1r[i] + h2c[2 * jp + 0]) & DMASK], g0);
            atomicAdd(&bins[(h1r[i] + h2c[2 * jp + 1]) & DMASK], g1);
        }
    }

    if (offdiag) {
        // Orientation 2: (c1,c2) = (col channel, row channel).
        // value = G~[i][j] * t[i] * u[j],  t = s1*s2 at row ch, u = s1*s2 at col ch.
        int h1c[8], h2r[8];
        float t[8], u[8];
#pragma unroll
        for (int i = 0; i < 8; ++i) {
            h2r[i] = d_h[1][c1_0 + ao + i];
            t[i]   = d_s[0][c1_0 + ao + i] * d_s[1][c1_0 + ao + i];
        }
#pragma unroll
        for (int j = 0; j < 8; ++j) {
            h1c[j] = d_h[0][c2_0 + bo + j];
            u[j]   = d_s[0][c2_0 + bo + j] * d_s[1][c2_0 + bo + j];
        }
#pragma unroll
        for (int i = 0; i < 8; ++i) {
#pragma unroll
            for (int jp = 0; jp < 4; ++jp) {
                float g0, g1;
                unpack2(acc[i][jp], g0, g1);
                atomicAdd(&bins[(h1c[2 * jp + 0] + h2r[i]) & DMASK], g0 * t[i] * u[2 * jp + 0]);
                atomicAdd(&bins[(h1c[2 * jp + 1] + h2r[i]) & DMASK], g1 * t[i] * u[2 * jp + 1]);
            }
        }
    }
    __syncthreads();

    // Merge local bins into the per-image global accumulator.
    float* yb = d_yacc + (size_t)b * DPROJ;
    for (int l = tid; l < DPROJ; l += NTHR) {
        float v = bins[l];
        if (v != 0.f) atomicAdd(&yb[l], v);
    }
}

// ============================================================
// Kernel 4: signed sqrt + L2 normalize per image row.
// 1024 threads/CTA, 8 elems/thread held in registers (1 read, 1 write).
// ============================================================
__global__ __launch_bounds__(1024, 1)
void finalize_kernel(float* __restrict__ out) {
    __shared__ float red[32];
    const int b   = blockIdx.x;
    const int tid = threadIdx.x;
    const float* yb = d_yacc + (size_t)b * DPROJ;
    float* ob = out + (size_t)b * DPROJ;

    float t[8];
    float ss = 0.f;
#pragma unroll
    for (int i = 0; i < 2; ++i) {
        float4 v = ((const float4*)yb)[tid + i * 1024];
#pragma unroll
        for (int c = 0; c < 4; ++c) {
            float vv = ((const float*)&v)[c];
            float tt;
            if      (vv > 0.f) tt =  sqrtf( vv + 1e-8f);
            else if (vv < 0.f) tt = -sqrtf(-vv + 1e-8f);
            else               tt = 0.f;
            t[i * 4 + c] = tt;
            ss += tt * tt;
        }
    }
#pragma unroll
    for (int o = 16; o; o >>= 1) ss += __shfl_xor_sync(0xFFFFFFFFu, ss, o);
    if ((tid & 31) == 0) red[tid >> 5] = ss;
    __syncthreads();
    if (tid < 32) {
        float s = red[tid];
#pragma unroll
        for (int o = 16; o; o >>= 1) s += __shfl_xor_sync(0xFFFFFFFFu, s, o);
        if (tid == 0) red[0] = 1.f / fmaxf(sqrtf(s), 1e-12f);
    }
    __syncthreads();
    float inv = red[0];
#pragma unroll
    for (int i = 0; i < 2; ++i) {
        float4 w;
        w.x = t[i * 4 + 0] * inv;
        w.y = t[i * 4 + 1] * inv;
        w.z = t[i * 4 + 2] * inv;
        w.w = t[i * 4 + 3] * inv;
        ((float4*)ob)[tid + i * 1024] = w;
    }
}

// ============================================================
extern "C" void kernel_launch(void* const* d_in, const int* in_sizes, int n_in,
                              void* d_out, int out_size) {
    (void)in_sizes; (void)n_in; (void)out_size;
    const float* x  = (const float*)d_in[0];
    const float* S1 = (const float*)d_in[1];
    const float* S2 = (const float*)d_in[2];
    float* out = (float*)d_out;

    const int smem_bytes = (DPROJ + 2 * KT * XS + 2 * CH) * (int)sizeof(float);
    cudaFuncSetAttribute(gram_scatter,
                         cudaFuncAttributeMaxDynamicSharedMemorySize, smem_bytes);

    extract_kernel<<<128, 256>>>(S1, S2);
    zero_kernel<<<(BATCH * DPROJ / 4) / 256, 256>>>();
    gram_scatter<<<dim3(NTILES, BATCH), NTHR, smem_bytes>>>(x);
    finalize_kernel<<<BATCH, 1024>>>(out);
}